// round 17
// baseline (speedup 1.0000x reference)
#include <cuda_runtime.h>
#include <cuda_fp16.h>
#include <cstdint>

// Problem constants
#define Bb 2
#define Tt 4096
#define Dd 4096
#define Hh 32
#define HKV 8
#define DH 128
#define Mrows 8192         // B*T
#define Ncols 6144         // D + 2*HKV*DH
#define Kdim 4096

// GEMM tiling (fp16 legacy mma + ldmatrix), 256 thr = 8 warps (2Mx4N), warp 64x32
#define BM 128
#define BN 128
#define BK 64
#define NKITER (Kdim / BK)            // 64
#define STAGES 3
#define A_STAGE_BYTES (BM * BK * 2)   // 16384
#define B_STAGE_BYTES (BN * BK * 2)   // 16384  (B staged [n][k], 128B rows)
#define SMEM_BYTES (STAGES * (A_STAGE_BYTES + B_STAGE_BYTES))  // 98304

#define MT (Mrows / BM)   // 64
#define NT (Ncols / BN)   // 48
#define GM 16

// merged prep kernel block ranges — rope FIRST so its fp64 latency overlaps
#define RBLOCKS 1024      // rope table: 4096*64 / 256
#define WBLOCKS 3072      // W transpose: (4096/64)k x (6144/128)n tiles
#define XBLOCKS 8192      // x convert: 33.5M halves / (256 thr * 16 halves)

// Scratch device globals
__device__ __half g_Ch[(size_t)Mrows * Ncols];        // GEMM result fp16 (Q|K only used)
__device__ __half g_xh[(size_t)Mrows * Kdim];         // fp16 x, [M,K] row-major
__device__ __half g_Wt[(size_t)Ncols * Kdim];         // fp16 W^T, [N,K] row-major
__device__ float2 g_tab[Tt * (DH / 2)];               // RoPE (cos,sin) table

// ---------------------------------------------------------------------------
// PTX helpers
// ---------------------------------------------------------------------------
__device__ __forceinline__ void cp_async16(uint32_t dst, const void* src) {
    asm volatile("cp.async.cg.shared.global [%0], [%1], 16;\n" :: "r"(dst), "l"(src));
}
__device__ __forceinline__ void cp_commit() {
    asm volatile("cp.async.commit_group;\n" ::: "memory");
}
__device__ __forceinline__ void cp_wait1() {
    asm volatile("cp.async.wait_group 1;\n" ::: "memory");
}
__device__ __forceinline__ void ldmatrix_x4(uint32_t r[4], uint32_t addr) {
    asm volatile("ldmatrix.sync.aligned.m8n8.x4.shared.b16 {%0,%1,%2,%3}, [%4];"
                 : "=r"(r[0]), "=r"(r[1]), "=r"(r[2]), "=r"(r[3]) : "r"(addr));
}
__device__ __forceinline__ void ldmatrix_x4_trans(uint32_t r[4], uint32_t addr) {
    asm volatile("ldmatrix.sync.aligned.m8n8.x4.trans.shared.b16 {%0,%1,%2,%3}, [%4];"
                 : "=r"(r[0]), "=r"(r[1]), "=r"(r[2]), "=r"(r[3]) : "r"(addr));
}
__device__ __forceinline__ void mma_f16(float c[4], const uint32_t a[4], const uint32_t b[2]) {
    asm volatile(
        "mma.sync.aligned.m16n8k16.row.col.f32.f16.f16.f32 "
        "{%0,%1,%2,%3}, {%4,%5,%6,%7}, {%8,%9}, {%0,%1,%2,%3};"
        : "+f"(c[0]), "+f"(c[1]), "+f"(c[2]), "+f"(c[3])
        : "r"(a[0]), "r"(a[1]), "r"(a[2]), "r"(a[3]), "r"(b[0]), "r"(b[1]));
}
__device__ __forceinline__ uint32_t swz128(uint32_t off) {
    return off ^ ((off >> 3) & 0x70);   // 128B rows
}
__device__ __forceinline__ uint32_t swzB(uint32_t off) {
    return off ^ ((off >> 4) & 0x70);   // 256B rows
}

// ---------------------------------------------------------------------------
// Kernel 1: merged prep — RoPE table, W transpose (ldmatrix.trans), x->fp16
// ---------------------------------------------------------------------------
__global__ __launch_bounds__(256) void prep_kernel(
    const float* __restrict__ x,
    const float* __restrict__ Wq,
    const float* __restrict__ Wk,
    const float* __restrict__ Wv)
{
    __shared__ __half wt[64 * 128];     // 16KB: one 64k x 128n fp16 tile (swzB)
    const int bid = blockIdx.x;
    const int tid = threadIdx.x;

    if (bid < RBLOCKS) {
        // ---- RoPE cos/sin table ----
        int idx = bid * 256 + tid;
        int t = idx >> 6;
        int j = idx & 63;
        double inv = exp2(-((double)(2 * j)) * (1.0 / 128.0) * 13.287712379549449);
        double a = (double)t * inv;
        double red = remainder(a, 6.283185307179586477);
        float s, c;
        sincosf((float)red, &s, &c);
        g_tab[idx] = make_float2(c, s);
    } else if (bid < RBLOCKS + WBLOCKS) {
        // ---- W transpose + convert: 64k x 128n tile -> g_Wt[n][k] ----
        const int w = bid - RBLOCKS;
        const int k0 = (w / 48) * 64;
        const int n0 = (w % 48) * 128;
        const float* src;
        size_t ld;
        if (n0 < 4096)      { src = Wq + (size_t)k0 * 4096 + n0;          ld = 4096; }
        else if (n0 < 5120) { src = Wk + (size_t)k0 * 1024 + (n0 - 4096); ld = 1024; }
        else                { src = Wv + (size_t)k0 * 1024 + (n0 - 5120); ld = 1024; }

        char* wsm = reinterpret_cast<char*>(wt);
        #pragma unroll
        for (int i = 0; i < 8; i++) {
            int idx = tid + i * 256;        // 0..2047
            int k = idx >> 5;               // 0..63
            int nq = idx & 31;              // float4 index within 128 n
            float4 v = *reinterpret_cast<const float4*>(src + (size_t)k * ld + nq * 4);
            uint2 o;
            __half2 h;
            h = make_half2(__float2half_rn(v.x), __float2half_rn(v.y));
            o.x = *reinterpret_cast<uint32_t*>(&h);
            h = make_half2(__float2half_rn(v.z), __float2half_rn(v.w));
            o.y = *reinterpret_cast<uint32_t*>(&h);
            *reinterpret_cast<uint2*>(wsm + swzB(k * 256 + nq * 8)) = o;
        }
        __syncthreads();

        // register transpose: each warp handles 4 tiles of 16k x 16n
        const int lane = tid & 31;
        const int wrp = tid >> 5;
        const uint32_t sbase = (uint32_t)__cvta_generic_to_shared(wt);
        const int lk = (lane & 7) + ((lane >> 3) & 1) * 8;   // tile k row addr
        const int ln = ((lane >> 4) & 1) * 8;                // tile n half
        #pragma unroll
        for (int j = 0; j < 4; j++) {
            int tt = wrp * 4 + j;          // 0..31
            int k16 = (tt & 3) * 16;
            int n16 = (tt >> 2) * 16;
            uint32_t r[4];
            ldmatrix_x4_trans(r, sbase + swzB((k16 + lk) * 256 + (n16 + ln) * 2));
            // fragment mapping: reg i -> n = (lane>>2)+(i>>1)*8, k = (lane&3)*2+(i&1)*8
            int nl = n0 + n16 + (lane >> 2);
            int kl = k0 + k16 + (lane & 3) * 2;
            #pragma unroll
            for (int i2 = 0; i2 < 4; i2++) {
                size_t off = (size_t)(nl + (i2 >> 1) * 8) * Kdim + kl + (i2 & 1) * 8;
                *reinterpret_cast<uint32_t*>(g_Wt + off) = r[i2];
            }
        }
    } else {
        // ---- convert x -> fp16: 16 halves per thread (4 loads, 2 stores) ----
        size_t i = ((size_t)(bid - RBLOCKS - WBLOCKS) * 256 + tid) * 2;  // uint4 idx
        const float4* xp = reinterpret_cast<const float4*>(x) + 2 * i;
        float4 v0 = xp[0];
        float4 v1 = xp[1];
        float4 v2 = xp[2];
        float4 v3 = xp[3];
        uint4 o0, o1;
        __half2 h;
        h = make_half2(__float2half_rn(v0.x), __float2half_rn(v0.y)); o0.x = *reinterpret_cast<uint32_t*>(&h);
        h = make_half2(__float2half_rn(v0.z), __float2half_rn(v0.w)); o0.y = *reinterpret_cast<uint32_t*>(&h);
        h = make_half2(__float2half_rn(v1.x), __float2half_rn(v1.y)); o0.z = *reinterpret_cast<uint32_t*>(&h);
        h = make_half2(__float2half_rn(v1.z), __float2half_rn(v1.w)); o0.w = *reinterpret_cast<uint32_t*>(&h);
        h = make_half2(__float2half_rn(v2.x), __float2half_rn(v2.y)); o1.x = *reinterpret_cast<uint32_t*>(&h);
        h = make_half2(__float2half_rn(v2.z), __float2half_rn(v2.w)); o1.y = *reinterpret_cast<uint32_t*>(&h);
        h = make_half2(__float2half_rn(v3.x), __float2half_rn(v3.y)); o1.z = *reinterpret_cast<uint32_t*>(&h);
        h = make_half2(__float2half_rn(v3.z), __float2half_rn(v3.w)); o1.w = *reinterpret_cast<uint32_t*>(&h);
        reinterpret_cast<uint4*>(g_xh)[i]     = o0;
        reinterpret_cast<uint4*>(g_xh)[i + 1] = o1;
    }
}

// ---------------------------------------------------------------------------
// Kernel 2: fp16 GEMM  C = g_xh @ g_Wt^T  (ldmatrix + HMMA)  [R14 exact]
// Q/K tiles (nt<40) -> fp16 scratch; V tiles (nt>=40) -> fp32 output direct.
// ---------------------------------------------------------------------------
__global__ __launch_bounds__(256, 2) void gemm_kernel(float* __restrict__ out) {
    extern __shared__ char smem[];
    const uint32_t smem_base = (uint32_t)__cvta_generic_to_shared(smem);
    const uint32_t a_base = smem_base;                          // 3 x 16KB
    const uint32_t b_base = smem_base + STAGES * A_STAGE_BYTES; // 3 x 16KB

    int gid = blockIdx.x;
    int group = gid / (GM * NT);
    int rem = gid % (GM * NT);
    const int mt = group * GM + (rem % GM);
    const int nt = rem / GM;
    const int m0 = mt * BM;
    const int n0 = nt * BN;

    const int tid = threadIdx.x;
    const int lane = tid & 31;
    const int wid = tid >> 5;
    const int warp_m = wid & 1;   // 0..1, 64 rows
    const int warp_n = wid >> 1;  // 0..3, 32 cols

    float acc[4][4][4];
    #pragma unroll
    for (int i = 0; i < 4; i++)
        #pragma unroll
        for (int j = 0; j < 4; j++)
            #pragma unroll
            for (int r = 0; r < 4; r++)
                acc[i][j][r] = 0.0f;

    auto issue = [&](int ktile, int slot) {
        const int k0 = ktile * BK;
        const uint32_t a_dst = a_base + slot * A_STAGE_BYTES;
        const uint32_t b_dst = b_base + slot * B_STAGE_BYTES;
        const __half* a_src = g_xh + (size_t)m0 * Kdim + k0;
        const __half* b_src = g_Wt + (size_t)n0 * Kdim + k0;
        #pragma unroll
        for (int i = 0; i < 4; i++) {
            int idx = tid + i * 256;       // 0..1023
            int row = idx >> 3;            // 0..127
            int kq = idx & 7;              // 16B chunk within 128B row
            cp_async16(a_dst + swz128(row * 128 + kq * 16),
                       a_src + (size_t)row * Kdim + kq * 8);
        }
        #pragma unroll
        for (int i = 0; i < 4; i++) {
            int idx = tid + i * 256;
            int row = idx >> 3;
            int kq = idx & 7;
            cp_async16(b_dst + swz128(row * 128 + kq * 16),
                       b_src + (size_t)row * Kdim + kq * 8);
        }
        cp_commit();
    };

    issue(0, 0);
    issue(1, 1);

    // ldmatrix lane addressing
    const int a_row = warp_m * 64 + (lane & 15);                      // + mi*16
    const int a_ch  = lane >> 4;                                      // + ks*2
    const int b_row = warp_n * 32 + (lane & 7) + ((lane >> 4) << 3);  // + ng*16
    const int b_ch  = (lane >> 3) & 1;                                // + ks*2

    #pragma unroll 1
    for (int it = 0; it < NKITER; it++) {
        const int slot = it % STAGES;
        cp_wait1();
        __syncthreads();

        {
            int lt = it + 2;
            if (lt < NKITER) issue(lt, lt % STAGES);
            else             cp_commit();     // empty group keeps wait accounting
        }

        const uint32_t A_s = a_base + slot * A_STAGE_BYTES;
        const uint32_t B_s = b_base + slot * B_STAGE_BYTES;

        #pragma unroll
        for (int ks = 0; ks < 4; ks++) {
            uint32_t a[4][4], b[2][4];
            #pragma unroll
            for (int mi = 0; mi < 4; mi++)
                ldmatrix_x4(a[mi], A_s + swz128((a_row + mi * 16) * 128 +
                                                (ks * 2 + a_ch) * 16));
            #pragma unroll
            for (int ng = 0; ng < 2; ng++)
                ldmatrix_x4(b[ng], B_s + swz128((b_row + ng * 16) * 128 +
                                                (ks * 2 + b_ch) * 16));
            #pragma unroll
            for (int mi = 0; mi < 4; mi++) {
                #pragma unroll
                for (int ng = 0; ng < 2; ng++) {
                    mma_f16(acc[mi][ng * 2],     a[mi], &b[ng][0]);
                    mma_f16(acc[mi][ng * 2 + 1], a[mi], &b[ng][2]);
                }
            }
        }
    }

    if (nt < 40) {
        // Q/K tiles: write accumulators to fp16 scratch C
        const int nbase = n0 + warp_n * 32;
        #pragma unroll
        for (int mi = 0; mi < 4; mi++) {
            int row = m0 + warp_m * 64 + mi * 16 + (lane >> 2);
            #pragma unroll
            for (int ni = 0; ni < 4; ni++) {
                int col = nbase + ni * 8 + (lane & 3) * 2;
                __half* p = g_Ch + (size_t)row * Ncols + col;
                *reinterpret_cast<__half2*>(p) =
                    make_half2(__float2half_rn(acc[mi][ni][0]),
                               __float2half_rn(acc[mi][ni][1]));
                *reinterpret_cast<__half2*>(p + (size_t)8 * Ncols) =
                    make_half2(__float2half_rn(acc[mi][ni][2]),
                               __float2half_rn(acc[mi][ni][3]));
            }
        }
    } else {
        // V tiles: direct fp32 store to out[v], transposed + repeated 4x
        float* outv = out + (size_t)67108864;   // 2*B*H*T*DH
        const int vbase = (n0 - 5120) + warp_n * 32;
        #pragma unroll
        for (int mi = 0; mi < 4; mi++) {
            int row0 = m0 + warp_m * 64 + mi * 16 + (lane >> 2);
            #pragma unroll
            for (int hf = 0; hf < 2; hf++) {
                int row = row0 + hf * 8;
                int b = row >> 12;
                int t = row & 4095;
                #pragma unroll
                for (int ni = 0; ni < 4; ni++) {
                    int col = vbase + ni * 8 + (lane & 3) * 2;
                    int d = col & 127;
                    int kh = col >> 7;
                    float2 val = hf == 0
                        ? make_float2(acc[mi][ni][0], acc[mi][ni][1])
                        : make_float2(acc[mi][ni][2], acc[mi][ni][3]);
                    #pragma unroll
                    for (int rr = 0; rr < 4; rr++) {
                        size_t off = (((size_t)(b * Hh + kh * 4 + rr) * Tt + t)
                                      * DH + d);
                        __stcs(reinterpret_cast<float2*>(outv + off), val);
                    }
                }
            }
        }
    }
}

// ---------------------------------------------------------------------------
// Kernel 3: per-token epilogue — 2 tokens per block, TWO-PASS rmsnorm to cut
// register pressure (pass 1: ssq only; pass 2: re-read Q from L1/L2).
// ---------------------------------------------------------------------------
__global__ __launch_bounds__(256) void epilogue_kernel(
    const float* __restrict__ gq,
    const float* __restrict__ gk,
    float* __restrict__ out)
{
    const int tid = threadIdx.x;
    const int lane = tid & 31;
    const int wid = tid >> 5;

    int bt[2];
    bt[0] = blockIdx.x * 2;
    bt[1] = bt[0] + 1;

    // ---- pass 1: sums of squares (Q values discarded; K kept in regs) ----
    float ssq_q[2], ssq_k[2], kf[2][4];
    #pragma unroll
    for (int s = 0; s < 2; s++) {
        const __half* row = g_Ch + (size_t)bt[s] * Ncols;
        const uint4* qp = reinterpret_cast<const uint4*>(row + tid * 16);
        float sq = 0.0f;
        #pragma unroll
        for (int c = 0; c < 2; c++) {
            uint4 u = qp[c];
            uint32_t* uu = reinterpret_cast<uint32_t*>(&u);
            #pragma unroll
            for (int j = 0; j < 4; j++) {
                __half2 h = *reinterpret_cast<__half2*>(&uu[j]);
                float2 f = __half22float2(h);
                sq += f.x * f.x + f.y * f.y;
            }
        }
        ssq_q[s] = sq;
        uint2 ku = *reinterpret_cast<const uint2*>(row + 4096 + tid * 4);
        __half2 h;
        h = *reinterpret_cast<__half2*>(&ku.x);
        kf[s][0] = __low2float(h); kf[s][1] = __high2float(h);
        h = *reinterpret_cast<__half2*>(&ku.y);
        kf[s][2] = __low2float(h); kf[s][3] = __high2float(h);
        ssq_k[s] = kf[s][0] * kf[s][0] + kf[s][1] * kf[s][1] +
                   kf[s][2] * kf[s][2] + kf[s][3] * kf[s][3];
    }

    #pragma unroll
    for (int o = 16; o > 0; o >>= 1) {
        ssq_q[0] += __shfl_xor_sync(0xFFFFFFFFu, ssq_q[0], o);
        ssq_q[1] += __shfl_xor_sync(0xFFFFFFFFu, ssq_q[1], o);
        ssq_k[0] += __shfl_xor_sync(0xFFFFFFFFu, ssq_k[0], o);
        ssq_k[1] += __shfl_xor_sync(0xFFFFFFFFu, ssq_k[1], o);
    }
    __shared__ float s_q[2][8], s_k[2][8];
    if (lane == 0) {
        s_q[0][wid] = ssq_q[0]; s_q[1][wid] = ssq_q[1];
        s_k[0][wid] = ssq_k[0]; s_k[1][wid] = ssq_k[1];
    }
    __syncthreads();
    float rs_q[2], rs_k[2];
    #pragma unroll
    for (int s = 0; s < 2; s++) {
        float tq = 0.0f, tk = 0.0f;
        #pragma unroll
        for (int i = 0; i < 8; i++) { tq += s_q[s][i]; tk += s_k[s][i]; }
        rs_q[s] = rsqrtf(tq * (1.0f / 4096.0f) + 1e-5f);
        rs_k[s] = rsqrtf(tk * (1.0f / 1024.0f) + 1e-5f);
    }

    // gamma loads shared across both tokens
    float gqv[16];
    {
        const float4* gp = reinterpret_cast<const float4*>(gq + tid * 16);
        #pragma unroll
        for (int i = 0; i < 4; i++) {
            float4 g4 = gp[i];
            gqv[4 * i] = g4.x; gqv[4 * i + 1] = g4.y;
            gqv[4 * i + 2] = g4.z; gqv[4 * i + 3] = g4.w;
        }
    }
    const float4 gk4 = *reinterpret_cast<const float4*>(gk + tid * 4);

    float* outq = out;
    float* outk = out + (size_t)33554432;   // B*H*T*DH

    // ---- pass 2: re-read Q (L1/L2 hits), scale+rope+write; K from regs ----
    #pragma unroll
    for (int s = 0; s < 2; s++) {
        const int b = bt[s] >> 12;
        const int t = bt[s] & 4095;
        const float2* tab = g_tab + t * 64;
        const __half* row = g_Ch + (size_t)bt[s] * Ncols;

        // ---- Q ----
        {
            const int h = tid >> 3;
            const int j0 = (tid * 8) & 63;
            const uint4* qp = reinterpret_cast<const uint4*>(row + tid * 16);
            float4* dst = reinterpret_cast<float4*>(
                outq + (((size_t)(b * Hh + h) * Tt + t) * DH + 2 * j0));
            #pragma unroll
            for (int c = 0; c < 2; c++) {
                uint4 u = qp[c];
                uint32_t* uu = reinterpret_cast<uint32_t*>(&u);
                float r[8];
                #pragma unroll
                for (int j = 0; j < 4; j++) {
                    __half2 hh = *reinterpret_cast<__half2*>(&uu[j]);
                    float2 f = __half22float2(hh);
                    int pi = c * 4 + j;                 // pair index 0..7
                    float2 cs = tab[j0 + pi];
                    float x1 = f.x * rs_q[s] * gqv[2 * pi];
                    float x2 = f.y * rs_q[s] * gqv[2 * pi + 1];
                    r[2 * j]     = x1 * cs.x - x2 * cs.y;
                    r[2 * j + 1] = x1 * cs.y + x2 * cs.x;
                }
                __stcs(dst + c * 2,     make_float4(r[0], r[1], r[2], r[3]));
                __stcs(dst + c * 2 + 1, make_float4(r[4], r[5], r[6], r[7]));
            }
        }

        // ---- K (repeated 4x) ----
        {
            const int kh = tid >> 5;
            const int j0 = (tid * 2) & 63;
            float2 cs0 = tab[j0];
            float2 cs1 = tab[j0 + 1];
            float x1 = kf[s][0] * rs_k[s] * gk4.x;
            float x2 = kf[s][1] * rs_k[s] * gk4.y;
            float y1 = kf[s][2] * rs_k[s] * gk4.z;
            float y2 = kf[s][3] * rs_k[s] * gk4.w;
            float4 r = make_float4(x1 * cs0.x - x2 * cs0.y, x1 * cs0.y + x2 * cs0.x,
                                   y1 * cs1.x - y2 * cs1.y, y1 * cs1.y + y2 * cs1.x);
            #pragma unroll
            for (int rr = 0; rr < 4; rr++) {
                int h = kh * 4 + rr;
                __stcs(reinterpret_cast<float4*>(
                    outk + (((size_t)(b * Hh + h) * Tt + t) * DH + 2 * j0)), r);
            }
        }
    }
}

// ---------------------------------------------------------------------------
extern "C" void kernel_launch(void* const* d_in, const int* in_sizes, int n_in,
                              void* d_out, int out_size)
{
    const float* x  = (const float*)d_in[0];
    const float* Wq = (const float*)d_in[1];
    const float* Wk = (const float*)d_in[2];
    const float* Wv = (const float*)d_in[3];
    const float* gq = (const float*)d_in[4];
    const float* gk = (const float*)d_in[5];
    float* out = (float*)d_out;

    cudaFuncSetAttribute(gemm_kernel,
                         cudaFuncAttributeMaxDynamicSharedMemorySize, SMEM_BYTES);

    prep_kernel<<<RBLOCKS + WBLOCKS + XBLOCKS, 256>>>(x, Wq, Wk, Wv);
    gemm_kernel<<<MT * NT, 256, SMEM_BYTES>>>(out);
    epilogue_kernel<<<Mrows / 2, 256>>>(gq, gk, out);
}